// round 10
// baseline (speedup 1.0000x reference)
#include <cuda_runtime.h>
#include <cstdint>

// ---------------------------------------------------------------------------
// out[2048,256] = x[2048,32768] @ W[32768,256],
// W[k,r] = U2[i2,r]*U1[i1,r]*U0[i0,r], k = i2*1024 + i1*32 + i0.
//
// tf32 m16n8k8 mma.sync. A: cp.async.cg (L1-bypass) global->smem raw fp32,
// 5-slot ring, 3 stages ahead (wait_group 3) -> DRAM latency hidden by
// pipeline depth, zero register staging. A fragments via ldmatrix.b16 on
// fp32 data (16B half-row trick). W never materialized: B fragments are
// cvt.rna.tf32(U2*U1*U0) computed in registers (single rounding).
// BN=64 warp tile 32x32, 2 CTAs/SM. Fused split-K reduction.
// ---------------------------------------------------------------------------

#define KT 32768
#define MT 2048
#define NT 256

#define SPLITS 4
#define KCH (KT / SPLITS)        // 8192
#define BK 32                    // one i0 period per stage (128 B fp32 / row)
#define NS (KCH / BK)            // 256 stages
#define BM 128
#define BN 64

#define SLOT_BYTES (BM * 128)    // 16 KB per stage
#define NBUF 5
#define SMEM_BYTES (NBUF * SLOT_BYTES)   // 80 KB

__device__ float g_part[SPLITS * MT * NT];        // 8 MB split-K partials
__device__ int   g_cnt[(MT / BM) * (NT / BN)];    // 64 tile counters

__device__ __forceinline__ uint32_t smem_u32(const void* p) {
    uint32_t a;
    asm("{ .reg .u64 t; cvta.to.shared.u64 t, %1; cvt.u32.u64 %0, t; }" : "=r"(a) : "l"(p));
    return a;
}
__device__ __forceinline__ uint32_t t32u(float x) {
    uint32_t u;
    asm("cvt.rna.tf32.f32 %0, %1;" : "=r"(u) : "f"(x));
    return u;
}
__device__ __forceinline__ void cp16(uint32_t dst, const void* src) {
    asm volatile("cp.async.cg.shared.global [%0], [%1], 16;" :: "r"(dst), "l"(src) : "memory");
}
__device__ __forceinline__ void ldm4(uint32_t* r, uint32_t addr) {
    asm volatile("ldmatrix.sync.aligned.m8n8.x4.shared.b16 {%0,%1,%2,%3}, [%4];"
                 : "=r"(r[0]), "=r"(r[1]), "=r"(r[2]), "=r"(r[3]) : "r"(addr));
}
__device__ __forceinline__ void mma1688(float* c, const uint32_t* a, uint32_t b0, uint32_t b1) {
    asm volatile(
        "mma.sync.aligned.m16n8k8.row.col.f32.tf32.tf32.f32 "
        "{%0,%1,%2,%3},{%4,%5,%6,%7},{%8,%9},{%0,%1,%2,%3};"
        : "+f"(c[0]), "+f"(c[1]), "+f"(c[2]), "+f"(c[3])
        : "r"(a[0]), "r"(a[1]), "r"(a[2]), "r"(a[3]), "r"(b0), "r"(b1));
}

// ---------------------------------------------------------------------------
__global__ __launch_bounds__(256, 2) void gemm_kernel(
    const float* __restrict__ x, const float* __restrict__ U0,
    const float* __restrict__ U1, const float* __restrict__ U2,
    float* __restrict__ out) {
    extern __shared__ char smem[];
    const uint32_t sb = smem_u32(smem);
    __shared__ int s_flag;

    const int tid  = threadIdx.x;
    const int lane = tid & 31;
    const int w    = tid >> 5;
    const int g    = lane >> 2;          // 0..7
    const int tg   = lane & 3;           // 0..3
    const int wm   = (w & 3) * 32;       // 4 warps along M (32 rows)
    const int wn   = (w >> 2) * 32;      // 2 warps along N (32 cols)
    const int m0   = blockIdx.x * BM;
    const int n0   = blockIdx.y * BN;
    const int z    = blockIdx.z;
    const long k0  = (long)z * KCH;

    // ---- fp32 U0 cache: u0c[nf][j] = U0[i0 = tg+4j, nc], nc = n0+wn+nf*8+g
    float u0c[4][8];
#pragma unroll
    for (int nf = 0; nf < 4; nf++) {
        const int nc = n0 + wn + nf * 8 + g;
#pragma unroll
        for (int j = 0; j < 8; j++)
            u0c[nf][j] = U0[(tg + 4 * j) * NT + nc];
    }

    // ---- A producer: thread -> row tid>>1, chunks c4..c4+3 (16B each) ----
    const int prow = tid >> 1;
    const int c4   = (tid & 1) * 4;
    const float* gx = x + (long)(m0 + prow) * KT + k0;
    uint32_t doff[4];
#pragma unroll
    for (int cc = 0; cc < 4; cc++)
        doff[cc] = (uint32_t)prow * 128 + (uint32_t)(((c4 + cc) ^ (prow & 7)) << 4);

    // ---- A consumer (ldmatrix-for-tf32): lane -> quad/row mapping ----
    const int q  = lane >> 3, j = lane & 7;        // quad, row-in-quad
    const uint32_t lrow0 = (uint32_t)(wm + (q & 1) * 8 + j) * 128;  // m16 tile 0
    const uint32_t lrow1 = lrow0 + 16 * 128;                        // m16 tile 1
    const int cb = q >> 1;                         // column-half of k8

    // ---- prologue: prefetch stages 0..2 ----
#pragma unroll
    for (int p = 0; p < 3; p++) {
        const uint32_t slot = sb + p * SLOT_BYTES;
#pragma unroll
        for (int cc = 0; cc < 4; cc++)
            cp16(slot + doff[cc], gx + p * BK + (c4 + cc) * 4);
        asm volatile("cp.async.commit_group;" ::: "memory");
    }

    float acc[2][4][4];
#pragma unroll
    for (int mf = 0; mf < 2; mf++)
#pragma unroll
        for (int nf = 0; nf < 4; nf++)
#pragma unroll
            for (int i = 0; i < 4; i++) acc[mf][nf][i] = 0.0f;

    for (int s = 0; s < NS; s++) {
        // prefetch stage s+3 into slot (s+3)%5 (writer never collides with
        // readers of slots s-1, s thanks to NBUF=5 + per-stage barrier)
        if (s + 3 < NS) {
            const uint32_t slot = sb + ((s + 3) % NBUF) * SLOT_BYTES;
            const float* gs = gx + (long)(s + 3) * BK;
#pragma unroll
            for (int cc = 0; cc < 4; cc++)
                cp16(slot + doff[cc], gs + (c4 + cc) * 4);
        }
        asm volatile("cp.async.commit_group;" ::: "memory");

        // this stage's W scalars: p12[nf] = U2[i2,nc] * U1[i1,nc]  (L1/L2 hits)
        const int i1 = s & 31;
        const int i2 = z * (KCH / 1024) + (s >> 5);
        float p12[4];
#pragma unroll
        for (int nf = 0; nf < 4; nf++) {
            const int nc = n0 + wn + nf * 8 + g;
            p12[nf] = U2[i2 * NT + nc] * U1[i1 * NT + nc];
        }

        asm volatile("cp.async.wait_group 3;" ::: "memory");
        __syncthreads();

        const uint32_t slotb = sb + (s % NBUF) * SLOT_BYTES;
#pragma unroll
        for (int ks = 0; ks < 4; ks++) {           // 4 x k8 per stage
            uint32_t a0[4], a1[4];
            const uint32_t csw = (uint32_t)(((2 * ks + cb) ^ j) << 4);
            ldm4(a0, slotb + lrow0 + csw);
            ldm4(a1, slotb + lrow1 + csw);
#pragma unroll
            for (int nf = 0; nf < 4; nf++) {
                const uint32_t b0 = t32u(p12[nf] * u0c[nf][2 * ks]);
                const uint32_t b1 = t32u(p12[nf] * u0c[nf][2 * ks + 1]);
                mma1688(acc[0][nf], a0, b0, b1);
                mma1688(acc[1][nf], a1, b0, b1);
            }
        }
    }

    // ---- write split partials ----
    float* part = g_part + (long)z * MT * NT;
#pragma unroll
    for (int mf = 0; mf < 2; mf++) {
        const int mr = m0 + wm + mf * 16 + g;
#pragma unroll
        for (int nf = 0; nf < 4; nf++) {
            const int nc = n0 + wn + nf * 8 + tg * 2;
            float2 v0, v1;
            v0.x = acc[mf][nf][0]; v0.y = acc[mf][nf][1];
            v1.x = acc[mf][nf][2]; v1.y = acc[mf][nf][3];
            *(float2*)&part[(long)mr * NT + nc]       = v0;
            *(float2*)&part[(long)(mr + 8) * NT + nc] = v1;
        }
    }

    // ---- fused split-K reduction: last CTA per (m,n) tile sums partials ----
    __threadfence();
    __syncthreads();
    if (tid == 0) {
        const int tile = blockIdx.x * (NT / BN) + blockIdx.y;
        const int old = atomicAdd(&g_cnt[tile], 1);
        s_flag = (old == SPLITS - 1);
        if (s_flag) g_cnt[tile] = 0;               // reset for next replay
    }
    __syncthreads();
    if (s_flag) {
        __threadfence();
#pragma unroll
        for (int jj = 0; jj < (BM * BN / 4) / 256; jj++) {   // 8 float4/thread
            const int f   = tid + 256 * jj;
            const int row = f >> 4;                 // 16 float4 per 64-col row
            const int cq  = f & 15;
            const long off = (long)(m0 + row) * NT + n0 + cq * 4;
            float4 sum = *(const float4*)(g_part + off);
#pragma unroll
            for (int zz = 1; zz < SPLITS; zz++) {
                const float4 v = *(const float4*)(g_part + (long)zz * MT * NT + off);
                sum.x += v.x; sum.y += v.y; sum.z += v.z; sum.w += v.w;
            }
            *(float4*)(out + off) = sum;
        }
    }
}

// ---------------------------------------------------------------------------
extern "C" void kernel_launch(void* const* d_in, const int* in_sizes, int n_in,
                              void* d_out, int out_size) {
    const float* x  = (const float*)d_in[0];
    const float* U0 = (const float*)d_in[1];
    const float* U1 = (const float*)d_in[2];
    const float* U2 = (const float*)d_in[3];
    float* out = (float*)d_out;

    static int smem_set = 0;
    if (!smem_set) {
        cudaFuncSetAttribute(gemm_kernel, cudaFuncAttributeMaxDynamicSharedMemorySize,
                             SMEM_BYTES);
        smem_set = 1;
    }

    dim3 grid(MT / BM, NT / BN, SPLITS);   // (16, 4, 4) = 256 CTAs, 2/SM
    gemm_kernel<<<grid, 256, SMEM_BYTES>>>(x, U0, U1, U2, out);
}

// round 12
// speedup vs baseline: 1.6917x; 1.6917x over previous
#include <cuda_runtime.h>
#include <cuda_fp16.h>
#include <cstdint>

// ---------------------------------------------------------------------------
// out[2048,256] = x[2048,32768] @ W[32768,256],
// W[k,r] = U2[i2,r]*U1[i1,r]*U0[i0,r], k = i2*1024 + i1*32 + i0.
//
// fp16 m16n8k16, fp32 accumulate. L1-traffic-minimized tiling:
//   BN=256 (full N -> x LDG'd/STS'd exactly once),
//   warp tile 32x64 (8 warps = 2M x 4N -> ldmatrix dup only 4x).
// L1 bytes: 268(LDG)+134(STS)+536(LDS) MB = 0.94 GB vs 2.7 GB in round 9.
// BM=64, BK=32, 3-slot smem ring (pitch 80 -> conflict-free ldmatrix),
// SPLITS=8 -> 256 CTAs @ 2/SM. W register-computed; fused split-K reduce.
// ---------------------------------------------------------------------------

#define KT 32768
#define MT 2048
#define NT 256

#define SPLITS 8
#define KCH (KT / SPLITS)        // 4096
#define BK 32
#define NS (KCH / BK)            // 128 stages
#define BM 64

#define PITCH 80                 // bytes per A row (64 data + 16 pad)
#define SLOT_BYTES (BM * PITCH)  // 5120

__device__ float g_part[SPLITS * MT * NT];   // 16 MB split-K partials
__device__ int   g_cnt[MT / BM];             // 32 tile counters (zero-init)

__device__ __forceinline__ uint32_t smem_u32(const void* p) {
    uint32_t a;
    asm("{ .reg .u64 t; cvta.to.shared.u64 t, %1; cvt.u32.u64 %0, t; }" : "=r"(a) : "l"(p));
    return a;
}
__device__ __forceinline__ uint32_t pkh2(float lo, float hi) {
    __half2 h = __floats2half2_rn(lo, hi);
    return *reinterpret_cast<uint32_t*>(&h);
}
__device__ __forceinline__ uint32_t hm2(uint32_t a, uint32_t b) {
    __half2 r = __hmul2(*reinterpret_cast<__half2*>(&a), *reinterpret_cast<__half2*>(&b));
    return *reinterpret_cast<uint32_t*>(&r);
}
__device__ __forceinline__ void ldm4(uint32_t* r, uint32_t addr) {
    asm volatile("ldmatrix.sync.aligned.m8n8.x4.shared.b16 {%0,%1,%2,%3}, [%4];"
                 : "=r"(r[0]), "=r"(r[1]), "=r"(r[2]), "=r"(r[3]) : "r"(addr));
}
__device__ __forceinline__ void mma16816(float* c, const uint32_t* a, uint32_t b0, uint32_t b1) {
    asm volatile(
        "mma.sync.aligned.m16n8k16.row.col.f32.f16.f16.f32 "
        "{%0,%1,%2,%3},{%4,%5,%6,%7},{%8,%9},{%0,%1,%2,%3};"
        : "+f"(c[0]), "+f"(c[1]), "+f"(c[2]), "+f"(c[3])
        : "r"(a[0]), "r"(a[1]), "r"(a[2]), "r"(a[3]), "r"(b0), "r"(b1));
}

// ---------------------------------------------------------------------------
__global__ __launch_bounds__(256, 2) void gemm_kernel(
    const float* __restrict__ x, const float* __restrict__ U0,
    const float* __restrict__ U1, const float* __restrict__ U2,
    float* __restrict__ out) {
    __shared__ __align__(16) char smem[3 * SLOT_BYTES];
    __shared__ int s_flag;
    const uint32_t sb = smem_u32(smem);

    const int tid  = threadIdx.x;
    const int lane = tid & 31;
    const int w    = tid >> 5;
    const int g    = lane >> 2;          // 0..7
    const int tg   = lane & 3;           // 0..3
    const int wm   = (w & 1) * 32;       // 2 warps along M (32 rows each)
    const int wn   = (w >> 1) * 64;      // 4 warps along N (64 cols each)
    const int m0   = blockIdx.x * BM;
    const int z    = blockIdx.y;
    const long k0  = (long)z * KCH;

    // ---- half2 U0 cache: u0h[nf][ks][h] covers i0 = ks*16 + 2tg + 8h + {0,1}
    uint32_t u0h[8][2][2];
#pragma unroll
    for (int nf = 0; nf < 8; nf++) {
        const int nc = wn + nf * 8 + g;
#pragma unroll
        for (int ks = 0; ks < 2; ks++)
#pragma unroll
            for (int h = 0; h < 2; h++) {
                const int i0 = ks * 16 + 2 * tg + 8 * h;
                u0h[nf][ks][h] = pkh2(U0[i0 * NT + nc], U0[(i0 + 1) * NT + nc]);
            }
    }

    // ---- A producer: thread -> (row = tid>>2, 8 contiguous k at c*8) ----
    const int prow = tid >> 2;           // 0..63
    const int pc   = tid & 3;            // 0..3
    const float* gx = x + (long)(m0 + prow) * KT + k0 + pc * 8;
    const uint32_t sts0 = (uint32_t)prow * PITCH + (uint32_t)pc * 16;

    // ---- A consumer (ldmatrix): lane -> row/chunk ----
    const int q = lane >> 3, jj = lane & 7;
    const uint32_t lrow0 = (uint32_t)(wm + (q & 1) * 8 + jj) * PITCH;  // m16 tile 0
    const uint32_t lrow1 = lrow0 + 16 * PITCH;                         // m16 tile 1
    const int cq = q >> 1;               // chunk half within k16

    // ---- prologue: stage 0 -> slot 0; xr <- stage 1 ----
    float4 xa = *(const float4*)(gx);
    float4 xb = *(const float4*)(gx + 4);
    {
        uint4 v;
        v.x = pkh2(xa.x, xa.y); v.y = pkh2(xa.z, xa.w);
        v.z = pkh2(xb.x, xb.y); v.w = pkh2(xb.z, xb.w);
        *(uint4*)(smem + sts0) = v;
    }
    xa = *(const float4*)(gx + BK);
    xb = *(const float4*)(gx + BK + 4);

    float acc[2][8][4];
#pragma unroll
    for (int mf = 0; mf < 2; mf++)
#pragma unroll
        for (int nf = 0; nf < 8; nf++)
#pragma unroll
            for (int i = 0; i < 4; i++) acc[mf][nf][i] = 0.0f;

    for (int s = 0; s < NS; s++) {
        // store stage s+1 (loaded at iter s-1) -> slot (s+1)%3
        if (s + 1 < NS) {
            uint4 v;
            v.x = pkh2(xa.x, xa.y); v.y = pkh2(xa.z, xa.w);
            v.z = pkh2(xb.x, xb.y); v.w = pkh2(xb.z, xb.w);
            *(uint4*)(smem + ((s + 1) % 3) * SLOT_BYTES + sts0) = v;
        }
        // load stage s+2 into regs (~1 full stage of latency coverage)
        if (s + 2 < NS) {
            const float* gs = gx + (long)(s + 2) * BK;
            xa = *(const float4*)(gs);
            xb = *(const float4*)(gs + 4);
        }

        // per-stage W scalars (U1/U2 are L1-resident)
        const int i1 = s & 31;
        const int i2 = z * (KCH / 1024) + (s >> 5);
        uint32_t p12h[8];
#pragma unroll
        for (int nf = 0; nf < 8; nf++) {
            const int nc = wn + nf * 8 + g;
            const float p = U2[i2 * NT + nc] * U1[i1 * NT + nc];
            p12h[nf] = pkh2(p, p);
        }

        __syncthreads();

        const uint32_t slotb = sb + (s % 3) * SLOT_BYTES;
#pragma unroll
        for (int ks = 0; ks < 2; ks++) {
            uint32_t a0[4], a1[4];
            const uint32_t csw = (uint32_t)((ks * 2 + cq) << 4);
            ldm4(a0, slotb + lrow0 + csw);
            ldm4(a1, slotb + lrow1 + csw);
#pragma unroll
            for (int nf = 0; nf < 8; nf++) {
                const uint32_t b0 = hm2(p12h[nf], u0h[nf][ks][0]);
                const uint32_t b1 = hm2(p12h[nf], u0h[nf][ks][1]);
                mma16816(acc[0][nf], a0, b0, b1);
                mma16816(acc[1][nf], a1, b0, b1);
            }
        }
    }

    // ---- write split partials ----
    float* part = g_part + (long)z * MT * NT;
#pragma unroll
    for (int mf = 0; mf < 2; mf++) {
        const int mr = m0 + wm + mf * 16 + g;
#pragma unroll
        for (int nf = 0; nf < 8; nf++) {
            const int nc = wn + nf * 8 + tg * 2;
            float2 v0, v1;
            v0.x = acc[mf][nf][0]; v0.y = acc[mf][nf][1];
            v1.x = acc[mf][nf][2]; v1.y = acc[mf][nf][3];
            *(float2*)&part[(long)mr * NT + nc]       = v0;
            *(float2*)&part[(long)(mr + 8) * NT + nc] = v1;
        }
    }

    // ---- fused split-K reduction: last CTA per M-tile sums partials ----
    __threadfence();
    __syncthreads();
    if (tid == 0) {
        const int old = atomicAdd(&g_cnt[blockIdx.x], 1);
        s_flag = (old == SPLITS - 1);
        if (s_flag) g_cnt[blockIdx.x] = 0;       // reset for next replay
    }
    __syncthreads();
    if (s_flag) {
        __threadfence();
#pragma unroll
        for (int it = 0; it < (BM * NT / 4) / 256; it++) {   // 16 float4/thread
            const int f   = tid + 256 * it;
            const int row = f >> 6;               // 64 float4 per 256-col row
            const int c4  = f & 63;
            const long off = (long)(m0 + row) * NT + c4 * 4;
            float4 sum = *(const float4*)(g_part + off);
#pragma unroll
            for (int zz = 1; zz < SPLITS; zz++) {
                const float4 v = *(const float4*)(g_part + (long)zz * MT * NT + off);
                sum.x += v.x; sum.y += v.y; sum.z += v.z; sum.w += v.w;
            }
            *(float4*)(out + off) = sum;
        }
    }
}

// ---------------------------------------------------------------------------
extern "C" void kernel_launch(void* const* d_in, const int* in_sizes, int n_in,
                              void* d_out, int out_size) {
    const float* x  = (const float*)d_in[0];
    const float* U0 = (const float*)d_in[1];
    const float* U1 = (const float*)d_in[2];
    const float* U2 = (const float*)d_in[3];
    float* out = (float*)d_out;

    dim3 grid(MT / BM, SPLITS);   // (32, 8) = 256 CTAs, 2/SM
    gemm_kernel<<<grid, 256>>>(x, U0, U1, U2, out);
}